// round 16
// baseline (speedup 1.0000x reference)
#include <cuda_runtime.h>
#include <cuda_fp16.h>
#include <cstdint>

#define TB 4
#define TS 2048
#define TH 16
#define TD 64
#define TC 1024

// ---------------------------------------------------------------------------
// Scratch (alloc-free rule: __device__ globals)
// ---------------------------------------------------------------------------
static __device__ __half g_qkvh[(size_t)8192 * 3072];        // [B*S, 3*C] fp16
static __device__ float g_entpad[4];
static __device__ __half g_xs[(size_t)8192 * 1024];          // x single fp16
static __device__ __half g_wq[(size_t)3072 * 1024];          // w_qkv^T [N,K]
static __device__ __half g_cs[(size_t)8192 * 1024];          // ctx single fp16
static __device__ __half g_wp[(size_t)1024 * 1024];          // w_proj^T [N,K]
// attention operands, [b,h,s,d] layout (contiguous 64-elem rows)
#define NBH ((size_t)TB * TH * TS * 64)
static __device__ __half g_qh2[NBH];                          // Q (LN'd, pre-scaled)
static __device__ __half g_kh2[NBH];                          // K (LN'd)
static __device__ __half g_vh2[NBH];                          // V

// ---------------------------------------------------------------------------
// Helpers (sm_103 base target: ldmatrix + mma.sync + cp.async only)
// ---------------------------------------------------------------------------
__device__ __forceinline__ uint32_t smem_u32(const void* p) {
    uint32_t a;
    asm("{ .reg .u64 t; cvta.to.shared.u64 t, %1; cvt.u32.u64 %0, t; }" : "=r"(a) : "l"(p));
    return a;
}
__device__ __forceinline__ uint32_t sw128(uint32_t off) { return off ^ ((off >> 3) & 0x70); }

__device__ __forceinline__ void cp16(uint32_t saddr, const void* gptr) {
    asm volatile("cp.async.cg.shared.global [%0], [%1], 16;" :: "r"(saddr), "l"(gptr));
}
__device__ __forceinline__ void cp_commit() {
    asm volatile("cp.async.commit_group;" ::: "memory");
}
template <int N>
__device__ __forceinline__ void cp_wait() {
    asm volatile("cp.async.wait_group %0;" :: "n"(N) : "memory");
}

__device__ __forceinline__ void ldm_x4(uint32_t addr, uint32_t r[4]) {
    asm volatile("ldmatrix.sync.aligned.m8n8.x4.shared.b16 {%0,%1,%2,%3}, [%4];"
                 : "=r"(r[0]), "=r"(r[1]), "=r"(r[2]), "=r"(r[3]) : "r"(addr));
}
__device__ __forceinline__ void ldm_x4_t(uint32_t addr, uint32_t r[4]) {
    asm volatile("ldmatrix.sync.aligned.m8n8.x4.trans.shared.b16 {%0,%1,%2,%3}, [%4];"
                 : "=r"(r[0]), "=r"(r[1]), "=r"(r[2]), "=r"(r[3]) : "r"(addr));
}

__device__ __forceinline__ void mma16816(float d[4], const uint32_t a[4], const uint32_t b[2]) {
    asm volatile(
        "mma.sync.aligned.m16n8k16.row.col.f32.f16.f16.f32 "
        "{%0,%1,%2,%3}, {%4,%5,%6,%7}, {%8,%9}, {%0,%1,%2,%3};"
        : "+f"(d[0]), "+f"(d[1]), "+f"(d[2]), "+f"(d[3])
        : "r"(a[0]), "r"(a[1]), "r"(a[2]), "r"(a[3]), "r"(b[0]), "r"(b[1]));
}

// pack two floats into fp16x2 (a = low, b = high)
__device__ __forceinline__ uint32_t cvt2h(float a, float b) {
    __half2 h = __floats2half2_rn(a, b);
    return *(uint32_t*)&h;
}

// ---------------------------------------------------------------------------
// Fused prep kernel (block-range partitioned):
//   [0, NCVT)  : x fp32 -> fp16 ; then w_qkv / w_proj transposes ; last: ent=0
// ---------------------------------------------------------------------------
#define PREP_NCVT 8192
#define PREP_NWQ  (96 * 32)
#define PREP_NWP  (32 * 32)
#define PREP_BLOCKS (PREP_NCVT + PREP_NWQ + PREP_NWP + 1)

__global__ __launch_bounds__(256) void prep_kernel(
    const float4* __restrict__ x4, __half* __restrict__ xs,
    const float* __restrict__ wq_src, __half* __restrict__ wq,
    const float* __restrict__ wp_src, __half* __restrict__ wp,
    float* __restrict__ ent)
{
    __shared__ float t[32][33];
    const int bx = blockIdx.x;
    const int tid = threadIdx.x;

    if (bx < PREP_NCVT) {
        int i = bx * 256 + tid;
        float4 v = x4[i];
        ((uint2*)xs)[i] = make_uint2(cvt2h(v.x, v.y), cvt2h(v.z, v.w));
        return;
    }
    const float* src;
    __half* dst;
    int K, N, n0, k0;
    if (bx < PREP_NCVT + PREP_NWQ) {
        int idx = bx - PREP_NCVT;
        src = wq_src; dst = wq; K = TC; N = 3 * TC;
        n0 = (idx % 96) << 5; k0 = (idx / 96) << 5;
    } else if (bx < PREP_NCVT + PREP_NWQ + PREP_NWP) {
        int idx = bx - PREP_NCVT - PREP_NWQ;
        src = wp_src; dst = wp; K = TC; N = TC;
        n0 = (idx % 32) << 5; k0 = (idx / 32) << 5;
    } else {
        if (tid < TB) ent[tid] = 0.f;
        return;
    }
    const int tx = tid & 31, ty = tid >> 5;
#pragma unroll
    for (int j = 0; j < 32; j += 8)
        t[ty + j][tx] = src[(size_t)(k0 + ty + j) * N + n0 + tx];
    __syncthreads();
#pragma unroll
    for (int j = 0; j < 32; j += 8) {
        size_t o = (size_t)(n0 + ty + j) * K + k0 + tx;
        dst[o] = __float2half_rn(t[tx][ty + j]);
    }
}

// ---------------------------------------------------------------------------
// Single-operand fp16 GEMM core (CTA 128x128, K-tile 64, 8 warps, 2-stage).
// ---------------------------------------------------------------------------
#define SS_A 0
#define SS_B 16384
#define SS_BUF 32768
#define GEMM_S_SMEM (2 * SS_BUF)

#define GEMM_BODY(A_, B_, K_)                                                   \
    extern __shared__ char smem[];                                              \
    const uint32_t sb = smem_u32(smem);                                         \
    const int tid = threadIdx.x;                                                \
    const int wid = tid >> 5;                                                   \
    const int lane = tid & 31;                                                  \
    const int row0 = blockIdx.y << 7;                                           \
    const int col0 = blockIdx.x << 7;                                           \
    const int wm = (wid & 1) << 6;                                              \
    const int wn = (wid >> 1) << 5;                                             \
    const int lr0 = tid >> 1;                                                   \
    const int lk0 = (tid & 1) << 2;                                             \
    float acc[4][4][4];                                                         \
    _Pragma("unroll")                                                           \
    for (int mt = 0; mt < 4; ++mt)                                              \
        _Pragma("unroll")                                                       \
        for (int nt = 0; nt < 4; ++nt)                                          \
            _Pragma("unroll")                                                   \
            for (int r = 0; r < 4; ++r) acc[mt][nt][r] = 0.f;                   \
    const int nk = (K_) >> 6;                                                   \
    auto load_tile = [&](int kb, int buf) {                                     \
        const uint32_t s0 = sb + buf * SS_BUF;                                  \
        _Pragma("unroll")                                                       \
        for (int cc = 0; cc < 4; ++cc) {                                        \
            const int r = lr0;                                                  \
            const int k8 = lk0 + cc;                                            \
            const size_t offA = (size_t)(row0 + r) * (K_) + kb + (k8 << 3);     \
            const size_t offB = (size_t)(col0 + r) * (K_) + kb + (k8 << 3);     \
            const uint32_t so = sw128((uint32_t)((r << 7) + (k8 << 4)));        \
            cp16(s0 + SS_A + so, (A_) + offA);                                  \
            cp16(s0 + SS_B + so, (B_) + offB);                                  \
        }                                                                       \
        cp_commit();                                                            \
    };                                                                          \
    load_tile(0, 0);                                                            \
    const int la_r = lane & 15;                                                 \
    const int la_c = lane >> 4;                                                 \
    const int lb_r = ((lane >> 4) << 3) + (lane & 7);                           \
    const int lb_c = (lane >> 3) & 1;                                           \
    for (int it = 0; it < nk; ++it) {                                           \
        if (it + 1 < nk) { load_tile((it + 1) << 6, (it + 1) & 1); cp_wait<1>(); } \
        else             { cp_wait<0>(); }                                      \
        __syncthreads();                                                        \
        const uint32_t s0 = sb + (it & 1) * SS_BUF;                             \
        _Pragma("unroll")                                                       \
        for (int ks = 0; ks < 4; ++ks) {                                        \
            uint32_t ah[4][4], bh[2][4];                                        \
            _Pragma("unroll")                                                   \
            for (int mt = 0; mt < 4; ++mt) {                                    \
                const uint32_t so = sw128((uint32_t)(((wm + (mt << 4) + la_r) << 7) \
                                    + (((ks << 1) + la_c) << 4)));              \
                ldm_x4(s0 + SS_A + so, ah[mt]);                                 \
            }                                                                   \
            _Pragma("unroll")                                                   \
            for (int p = 0; p < 2; ++p) {                                       \
                const uint32_t so = sw128((uint32_t)(((wn + (p << 4) + lb_r) << 7) \
                                    + (((ks << 1) + lb_c) << 4)));              \
                ldm_x4(s0 + SS_B + so, bh[p]);                                  \
            }                                                                   \
            _Pragma("unroll")                                                   \
            for (int mt = 0; mt < 4; ++mt)                                      \
                _Pragma("unroll")                                               \
                for (int nt = 0; nt < 4; ++nt)                                  \
                    mma16816(acc[mt][nt], ah[mt], &bh[nt >> 1][(nt & 1) << 1]); \
        }                                                                       \
        __syncthreads();                                                        \
    }                                                                           \
    const int g = lane >> 2, tg = lane & 3;

__global__ __launch_bounds__(256) void gemm_s_kernel(
    const __half* __restrict__ A, const __half* __restrict__ B,
    float* __restrict__ C, int M, int N, int K)
{
    GEMM_BODY(A, B, K)
#pragma unroll
    for (int mt = 0; mt < 4; ++mt)
#pragma unroll
        for (int nt = 0; nt < 4; ++nt) {
            const int row = row0 + wm + (mt << 4) + g;
            const int col = col0 + wn + (nt << 3) + (tg << 1);
            *(float2*)(C + (size_t)row * N + col) = make_float2(acc[mt][nt][0], acc[mt][nt][1]);
            *(float2*)(C + (size_t)(row + 8) * N + col) = make_float2(acc[mt][nt][2], acc[mt][nt][3]);
        }
}

__global__ __launch_bounds__(256) void gemm_sh_kernel(
    const __half* __restrict__ A, const __half* __restrict__ B,
    __half* __restrict__ C, int M, int N, int K)
{
    GEMM_BODY(A, B, K)
#pragma unroll
    for (int mt = 0; mt < 4; ++mt)
#pragma unroll
        for (int nt = 0; nt < 4; ++nt) {
            const int row = row0 + wm + (mt << 4) + g;
            const int col = col0 + wn + (nt << 3) + (tg << 1);
            ((uint32_t*)C)[((size_t)row * N + col) >> 1] = cvt2h(acc[mt][nt][0], acc[mt][nt][1]);
            ((uint32_t*)C)[((size_t)(row + 8) * N + col) >> 1] = cvt2h(acc[mt][nt][2], acc[mt][nt][3]);
        }
}

// ---------------------------------------------------------------------------
// Fused LayerNorm + convert from fp16 qkv: [b,s,3,h,d] ->
//   q: LN, *0.125 -> qh [b,h,s,d] ; k: LN -> kh ; v: copy -> vh
// ---------------------------------------------------------------------------
__global__ __launch_bounds__(256) void ln_split_kernel(
    const __half* __restrict__ qkv,
    const float* __restrict__ qs, const float* __restrict__ qbias,
    const float* __restrict__ ks, const float* __restrict__ kbias,
    __half* __restrict__ qh, __half* __restrict__ kh, __half* __restrict__ vh)
{
    const int w = (int)((blockIdx.x * 256u + threadIdx.x) >> 5);   // row over B*S*H
    const int lane = threadIdx.x & 31;
    const int h = w & 15;
    const int bs = w >> 4;
    const int b = bs >> 11, s = bs & 2047;
    const __half* p = qkv + (size_t)bs * 3072 + h * 64 + lane * 2;

    float2 qv = __half22float2(*(const __half2*)p);
    float2 kv = __half22float2(*(const __half2*)(p + 1024));
    uint32_t vw = *(const uint32_t*)(p + 2048);

    float sq = qv.x + qv.y, qq = qv.x * qv.x + qv.y * qv.y;
    float sk = kv.x + kv.y, kk = kv.x * kv.x + kv.y * kv.y;
#pragma unroll
    for (int off = 16; off; off >>= 1) {
        sq += __shfl_xor_sync(0xffffffffu, sq, off);
        qq += __shfl_xor_sync(0xffffffffu, qq, off);
        sk += __shfl_xor_sync(0xffffffffu, sk, off);
        kk += __shfl_xor_sync(0xffffffffu, kk, off);
    }
    float qm = sq * (1.f / 64.f);
    float qr = rsqrtf(fmaxf(qq * (1.f / 64.f) - qm * qm, 0.f) + 1e-5f);
    float km = sk * (1.f / 64.f);
    float kr = rsqrtf(fmaxf(kk * (1.f / 64.f) - km * km, 0.f) + 1e-5f);

    float2 scq = *(const float2*)(qs + lane * 2);
    float2 biq = *(const float2*)(qbias + lane * 2);
    float2 sck = *(const float2*)(ks + lane * 2);
    float2 bik = *(const float2*)(kbias + lane * 2);

    float qnx = ((qv.x - qm) * qr * scq.x + biq.x) * 0.125f;
    float qny = ((qv.y - qm) * qr * scq.y + biq.y) * 0.125f;
    float knx = (kv.x - km) * kr * sck.x + bik.x;
    float kny = (kv.y - km) * kr * sck.y + bik.y;

    const size_t o = (((size_t)(b * TH + h)) * TS + s) * 64 + lane * 2;
    *(uint32_t*)(qh + o) = cvt2h(qnx, qny);
    *(uint32_t*)(kh + o) = cvt2h(knx, kny);
    *(uint32_t*)(vh + o) = vw;
}

// ---------------------------------------------------------------------------
// Flash attention, MAX-FREE softmax (|logit| <= 8 from LN geometry).
// CTA: 128 q-rows, 4 warps, warp = m32 x n64. K-tile = 64 keys.
// __launch_bounds__(128, 3): cap regs at 170 -> 3 CTAs/SM (12 warps), the
// R15 profile showed 175 regs / 2 CTAs / issue 43% (latency-bound).
// Smem: double-buffered {K, V} (16KB/stage) + persistent Q (16KB) = 48KB.
// ---------------------------------------------------------------------------
#define AB_K  0
#define AB_VH 8192
#define AB_BUF 16384
#define AQ_H 32768
#define ATTN_SMEM 49152

__global__ __launch_bounds__(128, 3) void attn_mma_kernel(
    const __half* __restrict__ qhg, const __half* __restrict__ khg,
    const __half* __restrict__ vhg,
    __half* __restrict__ cs, float* __restrict__ ent)
{
    extern __shared__ char smA[];
    __shared__ float red[4];
    const uint32_t sb = smem_u32(smA);

    const int tid = threadIdx.x, wid = tid >> 5, lane = tid & 31;
    const int qb0 = blockIdx.x << 7;           // 128 q rows per CTA
    const int h = blockIdx.y, b = blockIdx.z;
    const size_t bh = ((size_t)(b * TH + h)) * TS * 64;

    // ---- prologue: Q (128 rows, 16KB) -> persistent region (group 0) ----
#pragma unroll
    for (int j = 0; j < 8; ++j) {
        int c = tid + 128 * j;
        int row = c >> 3, k8 = c & 7;
        size_t g = bh + (size_t)(qb0 + row) * 64 + (k8 << 3);
        uint32_t so = sw128((uint32_t)((row << 7) + (k8 << 4)));
        cp16(sb + AQ_H + so, qhg + g);
    }
    cp_commit();

    auto load_kv = [&](int kt) {
        const uint32_t bufb = sb + (uint32_t)(kt & 1) * AB_BUF;
#pragma unroll
        for (int j = 0; j < 4; ++j) {
            int c = tid + 128 * j;
            int row = c >> 3, k8 = c & 7;
            size_t g = bh + (size_t)((kt << 6) + row) * 64 + (k8 << 3);
            uint32_t so = sw128((uint32_t)((row << 7) + (k8 << 4)));
            cp16(bufb + AB_K + so, khg + g);
            cp16(bufb + AB_VH + so, vhg + g);
        }
        cp_commit();
    };
    load_kv(0);

    cp_wait<1>();                              // Q group retired (FIFO)
    __syncthreads();

    // ---- extract Q A-fragments (2 m16 sub-tiles) ----
    uint32_t qh[2][4][4];
    {
        const int cb = (lane >> 4) << 4;
#pragma unroll
        for (int mt = 0; mt < 2; ++mt) {
            const int row = (wid << 5) + (mt << 4) + (lane & 15);
#pragma unroll
            for (int s = 0; s < 4; ++s) {
                uint32_t so = sw128((uint32_t)(row * 128 + s * 32 + cb));
                ldm_x4(sb + AQ_H + so, qh[mt][s]);
            }
        }
    }

    float o[2][8][4];
#pragma unroll
    for (int mt = 0; mt < 2; ++mt)
#pragma unroll
        for (int nt = 0; nt < 8; ++nt)
#pragma unroll
            for (int r = 0; r < 4; ++r) o[mt][nt][r] = 0.f;
    float l2[2][2] = {{0.f, 0.f}, {0.f, 0.f}};
    float T2[2][2] = {{0.f, 0.f}, {0.f, 0.f}};

    for (int kt = 0; kt < TS / 64; ++kt) {
        if (kt + 1 < TS / 64) { load_kv(kt + 1); cp_wait<1>(); }
        else                  { cp_wait<0>(); }
        __syncthreads();
        const uint32_t bufb = sb + (uint32_t)(kt & 1) * AB_BUF;

        // ---- S = Q K^T : K frags loaded ONCE, used by both m-tiles ----
        float s4[2][8][4];
#pragma unroll
        for (int mt = 0; mt < 2; ++mt)
#pragma unroll
            for (int nt = 0; nt < 8; ++nt)
#pragma unroll
                for (int r = 0; r < 4; ++r) s4[mt][nt][r] = 0.f;

#pragma unroll
        for (int s = 0; s < 4; ++s) {
            uint32_t kb[4][4];
#pragma unroll
            for (int p = 0; p < 4; ++p) {
                const int kb_row = ((lane >> 4) << 3) + (lane & 7);
                const int kb_c = (lane >> 3) & 1;
                uint32_t so = sw128((uint32_t)(((p << 4) + kb_row) * 128 + s * 32 + kb_c * 16));
                ldm_x4(bufb + AB_K + so, kb[p]);
            }
#pragma unroll
            for (int mt = 0; mt < 2; ++mt)
#pragma unroll
                for (int nt = 0; nt < 8; ++nt)
                    mma16816(s4[mt][nt], qh[mt][s], &kb[nt >> 1][(nt & 1) << 1]);
        }

        // ---- max-free softmax accumulation (thread-local l, T) ----
#pragma unroll
        for (int mt = 0; mt < 2; ++mt) {
#pragma unroll
            for (int nt = 0; nt < 8; ++nt) {
                float d0 = s4[mt][nt][0], d1 = s4[mt][nt][1];
                float d2 = s4[mt][nt][2], d3 = s4[mt][nt][3];
                float e0 = __expf(d0), e1 = __expf(d1);
                float e2 = __expf(d2), e3 = __expf(d3);
                s4[mt][nt][0] = e0; s4[mt][nt][1] = e1;
                s4[mt][nt][2] = e2; s4[mt][nt][3] = e3;
                l2[mt][0] += e0 + e1;
                l2[mt][1] += e2 + e3;
                T2[mt][0] = fmaf(e0, d0, fmaf(e1, d1, T2[mt][0]));
                T2[mt][1] = fmaf(e2, d2, fmaf(e3, d3, T2[mt][1]));
            }
        }

        // ---- O += P V : V frags loaded ONCE, used by both m-tiles ----
#pragma unroll
        for (int s = 0; s < 4; ++s) {
            uint32_t pa[2][4];
#pragma unroll
            for (int mt = 0; mt < 2; ++mt) {
                pa[mt][0] = cvt2h(s4[mt][2 * s][0],     s4[mt][2 * s][1]);
                pa[mt][1] = cvt2h(s4[mt][2 * s][2],     s4[mt][2 * s][3]);
                pa[mt][2] = cvt2h(s4[mt][2 * s + 1][0], s4[mt][2 * s + 1][1]);
                pa[mt][3] = cvt2h(s4[mt][2 * s + 1][2], s4[mt][2 * s + 1][3]);
            }
            uint32_t vb[4][4];
#pragma unroll
            for (int p2 = 0; p2 < 4; ++p2) {
                const int v_key = (((lane >> 3) & 1) << 3) + (lane & 7);
                const int v_d = (lane >> 4) << 3;
                uint32_t so = sw128((uint32_t)(((s << 4) + v_key) * 128 + ((p2 << 4) + v_d) * 2));
                ldm_x4_t(bufb + AB_VH + so, vb[p2]);
            }
#pragma unroll
            for (int mt = 0; mt < 2; ++mt)
#pragma unroll
                for (int nt = 0; nt < 8; ++nt)
                    mma16816(o[mt][nt], pa[mt], &vb[nt >> 1][(nt & 1) << 1]);
        }
        __syncthreads();   // all warps done reading buf before next overwrite
    }

    // ---- final quad reduction of l, T (once, not per tile) ----
#pragma unroll
    for (int mt = 0; mt < 2; ++mt)
#pragma unroll
        for (int hf = 0; hf < 2; ++hf) {
#pragma unroll
            for (int off = 1; off <= 2; off <<= 1) {
                l2[mt][hf] += __shfl_xor_sync(0xffffffffu, l2[mt][hf], off);
                T2[mt][hf] += __shfl_xor_sync(0xffffffffu, T2[mt][hf], off);
            }
        }

    // ---- write context as single fp16 (feeds proj GEMM directly) ----
#pragma unroll
    for (int mt = 0; mt < 2; ++mt) {
        float rl0 = 1.f / l2[mt][0], rl1 = 1.f / l2[mt][1];
        const int r0 = qb0 + (wid << 5) + (mt << 4) + (lane >> 2);
        const int cb = (h << 6) + ((lane & 3) << 1);
#pragma unroll
        for (int nt = 0; nt < 8; ++nt) {
            const int col = cb + (nt << 3);
            const size_t i0 = ((size_t)(b * TS + r0) * 1024 + col) >> 1;
            const size_t i1 = ((size_t)(b * TS + r0 + 8) * 1024 + col) >> 1;
            ((uint32_t*)cs)[i0] = cvt2h(o[mt][nt][0] * rl0, o[mt][nt][1] * rl0);
            ((uint32_t*)cs)[i1] = cvt2h(o[mt][nt][2] * rl1, o[mt][nt][3] * rl1);
        }
    }

    // ---- entropy: per-row log(l) - T/l, reduce, one atomic per CTA ----
    float e = 0.f;
    if ((lane & 3) == 0) {
#pragma unroll
        for (int mt = 0; mt < 2; ++mt)
            e += (__logf(l2[mt][0]) - T2[mt][0] / l2[mt][0]) +
                 (__logf(l2[mt][1]) - T2[mt][1] / l2[mt][1]);
    }
#pragma unroll
    for (int off = 16; off; off >>= 1) e += __shfl_xor_sync(0xffffffffu, e, off);
    if (lane == 0) red[wid] = e;
    __syncthreads();
    if (tid == 0) {
        float esum = red[0] + red[1] + red[2] + red[3];
        const float ent_scale = (float)(1.0 / (7.6246189861593985 * (double)(TH * TS)));
        atomicAdd(ent + b, esum * ent_scale);
    }
}

// ---------------------------------------------------------------------------
extern "C" void kernel_launch(void* const* d_in, const int* in_sizes, int n_in,
                              void* d_out, int out_size)
{
    const float* x       = (const float*)d_in[0];
    const float* w_qkv   = (const float*)d_in[1];
    const float* w_proj  = (const float*)d_in[2];
    const float* q_scale = (const float*)d_in[3];
    const float* q_bias  = (const float*)d_in[4];
    const float* k_scale = (const float*)d_in[5];
    const float* k_bias  = (const float*)d_in[6];
    float* out = (float*)d_out;

    float* entpad;
    cudaGetSymbolAddress((void**)&entpad, g_entpad);
    __half *qkvh, *xs, *wq, *cs, *wp;
    __half *qh2, *kh2, *vh2;
    cudaGetSymbolAddress((void**)&qkvh, g_qkvh);
    cudaGetSymbolAddress((void**)&xs, g_xs);
    cudaGetSymbolAddress((void**)&wq, g_wq);
    cudaGetSymbolAddress((void**)&cs, g_cs);
    cudaGetSymbolAddress((void**)&wp, g_wp);
    cudaGetSymbolAddress((void**)&qh2, g_qh2);
    cudaGetSymbolAddress((void**)&kh2, g_kh2);
    cudaGetSymbolAddress((void**)&vh2, g_vh2);

    cudaFuncSetAttribute(gemm_s_kernel, cudaFuncAttributeMaxDynamicSharedMemorySize, GEMM_S_SMEM);
    cudaFuncSetAttribute(gemm_sh_kernel, cudaFuncAttributeMaxDynamicSharedMemorySize, GEMM_S_SMEM);
    cudaFuncSetAttribute(attn_mma_kernel, cudaFuncAttributeMaxDynamicSharedMemorySize, ATTN_SMEM);

    const int BS = TB * TS;                 // 8192
    const size_t main_elems = (size_t)BS * TC;
    float* ent = (out_size >= (int)(main_elems + TB)) ? (out + main_elems) : entpad;

    // 1) fused prep: x->fp16, w transposes, entropy zero
    prep_kernel<<<PREP_BLOCKS, 256>>>((const float4*)x, xs, w_qkv, wq, w_proj, wp, ent);

    // 2) QKV projection -> fp16 qkv: [8192,1024] @ [1024,3072]
    gemm_sh_kernel<<<dim3(3 * TC / 128, BS / 128), 256, GEMM_S_SMEM>>>(
        xs, wq, qkvh, BS, 3 * TC, TC);

    // 3) fused LayerNorm + convert -> fp16 q/k/v in [b,h,s,d]
    ln_split_kernel<<<(TB * TS * TH) / 8, 256>>>(
        qkvh, q_scale, q_bias, k_scale, k_bias, qh2, kh2, vh2);

    // 4) fused attention (max-free softmax) + entropy -> cs fp16 (3 CTA/SM)
    attn_mma_kernel<<<dim3(TS / 128, TH, TB), 128, ATTN_SMEM>>>(
        qh2, kh2, vh2, cs, ent);

    // 5) output projection (single fp16): [8192,1024] @ [1024,1024]
    gemm_s_kernel<<<dim3(TC / 128, BS / 128), 256, GEMM_S_SMEM>>>(
        cs, wp, out, BS, TC, TC);
}

// round 17
// speedup vs baseline: 1.4942x; 1.4942x over previous
#include <cuda_runtime.h>
#include <cuda_fp16.h>
#include <cstdint>

#define TB 4
#define TS 2048
#define TH 16
#define TD 64
#define TC 1024

// ---------------------------------------------------------------------------
// Scratch (alloc-free rule: __device__ globals)
// ---------------------------------------------------------------------------
static __device__ __half g_qkvh[(size_t)8192 * 3072];        // [B*S, 3*C] fp16
static __device__ float g_entpad[4];
static __device__ __half g_xs[(size_t)8192 * 1024];          // x single fp16
static __device__ __half g_wq[(size_t)3072 * 1024];          // w_qkv^T [N,K]
static __device__ __half g_cs[(size_t)8192 * 1024];          // ctx single fp16
static __device__ __half g_wp[(size_t)1024 * 1024];          // w_proj^T [N,K]
// attention operands, [b,h,s,d] layout (contiguous 64-elem rows)
#define NBH ((size_t)TB * TH * TS * 64)
static __device__ __half g_qh2[NBH];                          // Q (LN'd, pre-scaled)
static __device__ __half g_kh2[NBH];                          // K (LN'd)
static __device__ __half g_vh2[NBH];                          // V

// ---------------------------------------------------------------------------
// Helpers (sm_103 base target: ldmatrix + mma.sync + cp.async only)
// ---------------------------------------------------------------------------
__device__ __forceinline__ uint32_t smem_u32(const void* p) {
    uint32_t a;
    asm("{ .reg .u64 t; cvta.to.shared.u64 t, %1; cvt.u32.u64 %0, t; }" : "=r"(a) : "l"(p));
    return a;
}
__device__ __forceinline__ uint32_t sw128(uint32_t off) { return off ^ ((off >> 3) & 0x70); }

__device__ __forceinline__ void cp16(uint32_t saddr, const void* gptr) {
    asm volatile("cp.async.cg.shared.global [%0], [%1], 16;" :: "r"(saddr), "l"(gptr));
}
__device__ __forceinline__ void cp_commit() {
    asm volatile("cp.async.commit_group;" ::: "memory");
}
template <int N>
__device__ __forceinline__ void cp_wait() {
    asm volatile("cp.async.wait_group %0;" :: "n"(N) : "memory");
}

__device__ __forceinline__ void ldm_x4(uint32_t addr, uint32_t r[4]) {
    asm volatile("ldmatrix.sync.aligned.m8n8.x4.shared.b16 {%0,%1,%2,%3}, [%4];"
                 : "=r"(r[0]), "=r"(r[1]), "=r"(r[2]), "=r"(r[3]) : "r"(addr));
}
__device__ __forceinline__ void ldm_x4_t(uint32_t addr, uint32_t r[4]) {
    asm volatile("ldmatrix.sync.aligned.m8n8.x4.trans.shared.b16 {%0,%1,%2,%3}, [%4];"
                 : "=r"(r[0]), "=r"(r[1]), "=r"(r[2]), "=r"(r[3]) : "r"(addr));
}

__device__ __forceinline__ void mma16816(float d[4], const uint32_t a[4], const uint32_t b[2]) {
    asm volatile(
        "mma.sync.aligned.m16n8k16.row.col.f32.f16.f16.f32 "
        "{%0,%1,%2,%3}, {%4,%5,%6,%7}, {%8,%9}, {%0,%1,%2,%3};"
        : "+f"(d[0]), "+f"(d[1]), "+f"(d[2]), "+f"(d[3])
        : "r"(a[0]), "r"(a[1]), "r"(a[2]), "r"(a[3]), "r"(b[0]), "r"(b[1]));
}

// pack two floats into fp16x2 (a = low, b = high)
__device__ __forceinline__ uint32_t cvt2h(float a, float b) {
    __half2 h = __floats2half2_rn(a, b);
    return *(uint32_t*)&h;
}

// ---------------------------------------------------------------------------
// Fused prep kernel (block-range partitioned):
//   [0, NCVT)  : x fp32 -> fp16 ; then w_qkv / w_proj transposes ; last: ent=0
// ---------------------------------------------------------------------------
#define PREP_NCVT 8192
#define PREP_NWQ  (96 * 32)
#define PREP_NWP  (32 * 32)
#define PREP_BLOCKS (PREP_NCVT + PREP_NWQ + PREP_NWP + 1)

__global__ __launch_bounds__(256) void prep_kernel(
    const float4* __restrict__ x4, __half* __restrict__ xs,
    const float* __restrict__ wq_src, __half* __restrict__ wq,
    const float* __restrict__ wp_src, __half* __restrict__ wp,
    float* __restrict__ ent)
{
    __shared__ float t[32][33];
    const int bx = blockIdx.x;
    const int tid = threadIdx.x;

    if (bx < PREP_NCVT) {
        int i = bx * 256 + tid;
        float4 v = x4[i];
        ((uint2*)xs)[i] = make_uint2(cvt2h(v.x, v.y), cvt2h(v.z, v.w));
        return;
    }
    const float* src;
    __half* dst;
    int K, N, n0, k0;
    if (bx < PREP_NCVT + PREP_NWQ) {
        int idx = bx - PREP_NCVT;
        src = wq_src; dst = wq; K = TC; N = 3 * TC;
        n0 = (idx % 96) << 5; k0 = (idx / 96) << 5;
    } else if (bx < PREP_NCVT + PREP_NWQ + PREP_NWP) {
        int idx = bx - PREP_NCVT - PREP_NWQ;
        src = wp_src; dst = wp; K = TC; N = TC;
        n0 = (idx % 32) << 5; k0 = (idx / 32) << 5;
    } else {
        if (tid < TB) ent[tid] = 0.f;
        return;
    }
    const int tx = tid & 31, ty = tid >> 5;
#pragma unroll
    for (int j = 0; j < 32; j += 8)
        t[ty + j][tx] = src[(size_t)(k0 + ty + j) * N + n0 + tx];
    __syncthreads();
#pragma unroll
    for (int j = 0; j < 32; j += 8) {
        size_t o = (size_t)(n0 + ty + j) * K + k0 + tx;
        dst[o] = __float2half_rn(t[tx][ty + j]);
    }
}

// ---------------------------------------------------------------------------
// Single-operand fp16 GEMM core (CTA 128x128, K-tile 64, 8 warps, 2-stage).
// ---------------------------------------------------------------------------
#define SS_A 0
#define SS_B 16384
#define SS_BUF 32768
#define GEMM_S_SMEM (2 * SS_BUF)

#define GEMM_BODY(A_, B_, K_)                                                   \
    extern __shared__ char smem[];                                              \
    const uint32_t sb = smem_u32(smem);                                         \
    const int tid = threadIdx.x;                                                \
    const int wid = tid >> 5;                                                   \
    const int lane = tid & 31;                                                  \
    const int row0 = blockIdx.y << 7;                                           \
    const int col0 = blockIdx.x << 7;                                           \
    const int wm = (wid & 1) << 6;                                              \
    const int wn = (wid >> 1) << 5;                                             \
    const int lr0 = tid >> 1;                                                   \
    const int lk0 = (tid & 1) << 2;                                             \
    float acc[4][4][4];                                                         \
    _Pragma("unroll")                                                           \
    for (int mt = 0; mt < 4; ++mt)                                              \
        _Pragma("unroll")                                                       \
        for (int nt = 0; nt < 4; ++nt)                                          \
            _Pragma("unroll")                                                   \
            for (int r = 0; r < 4; ++r) acc[mt][nt][r] = 0.f;                   \
    const int nk = (K_) >> 6;                                                   \
    auto load_tile = [&](int kb, int buf) {                                     \
        const uint32_t s0 = sb + buf * SS_BUF;                                  \
        _Pragma("unroll")                                                       \
        for (int cc = 0; cc < 4; ++cc) {                                        \
            const int r = lr0;                                                  \
            const int k8 = lk0 + cc;                                            \
            const size_t offA = (size_t)(row0 + r) * (K_) + kb + (k8 << 3);     \
            const size_t offB = (size_t)(col0 + r) * (K_) + kb + (k8 << 3);     \
            const uint32_t so = sw128((uint32_t)((r << 7) + (k8 << 4)));        \
            cp16(s0 + SS_A + so, (A_) + offA);                                  \
            cp16(s0 + SS_B + so, (B_) + offB);                                  \
        }                                                                       \
        cp_commit();                                                            \
    };                                                                          \
    load_tile(0, 0);                                                            \
    const int la_r = lane & 15;                                                 \
    const int la_c = lane >> 4;                                                 \
    const int lb_r = ((lane >> 4) << 3) + (lane & 7);                           \
    const int lb_c = (lane >> 3) & 1;                                           \
    for (int it = 0; it < nk; ++it) {                                           \
        if (it + 1 < nk) { load_tile((it + 1) << 6, (it + 1) & 1); cp_wait<1>(); } \
        else             { cp_wait<0>(); }                                      \
        __syncthreads();                                                        \
        const uint32_t s0 = sb + (it & 1) * SS_BUF;                             \
        _Pragma("unroll")                                                       \
        for (int ks = 0; ks < 4; ++ks) {                                        \
            uint32_t ah[4][4], bh[2][4];                                        \
            _Pragma("unroll")                                                   \
            for (int mt = 0; mt < 4; ++mt) {                                    \
                const uint32_t so = sw128((uint32_t)(((wm + (mt << 4) + la_r) << 7) \
                                    + (((ks << 1) + la_c) << 4)));              \
                ldm_x4(s0 + SS_A + so, ah[mt]);                                 \
            }                                                                   \
            _Pragma("unroll")                                                   \
            for (int p = 0; p < 2; ++p) {                                       \
                const uint32_t so = sw128((uint32_t)(((wn + (p << 4) + lb_r) << 7) \
                                    + (((ks << 1) + lb_c) << 4)));              \
                ldm_x4(s0 + SS_B + so, bh[p]);                                  \
            }                                                                   \
            _Pragma("unroll")                                                   \
            for (int mt = 0; mt < 4; ++mt)                                      \
                _Pragma("unroll")                                               \
                for (int nt = 0; nt < 4; ++nt)                                  \
                    mma16816(acc[mt][nt], ah[mt], &bh[nt >> 1][(nt & 1) << 1]); \
        }                                                                       \
        __syncthreads();                                                        \
    }                                                                           \
    const int g = lane >> 2, tg = lane & 3;

__global__ __launch_bounds__(256) void gemm_s_kernel(
    const __half* __restrict__ A, const __half* __restrict__ B,
    float* __restrict__ C, int M, int N, int K)
{
    GEMM_BODY(A, B, K)
#pragma unroll
    for (int mt = 0; mt < 4; ++mt)
#pragma unroll
        for (int nt = 0; nt < 4; ++nt) {
            const int row = row0 + wm + (mt << 4) + g;
            const int col = col0 + wn + (nt << 3) + (tg << 1);
            *(float2*)(C + (size_t)row * N + col) = make_float2(acc[mt][nt][0], acc[mt][nt][1]);
            *(float2*)(C + (size_t)(row + 8) * N + col) = make_float2(acc[mt][nt][2], acc[mt][nt][3]);
        }
}

__global__ __launch_bounds__(256) void gemm_sh_kernel(
    const __half* __restrict__ A, const __half* __restrict__ B,
    __half* __restrict__ C, int M, int N, int K)
{
    GEMM_BODY(A, B, K)
#pragma unroll
    for (int mt = 0; mt < 4; ++mt)
#pragma unroll
        for (int nt = 0; nt < 4; ++nt) {
            const int row = row0 + wm + (mt << 4) + g;
            const int col = col0 + wn + (nt << 3) + (tg << 1);
            ((uint32_t*)C)[((size_t)row * N + col) >> 1] = cvt2h(acc[mt][nt][0], acc[mt][nt][1]);
            ((uint32_t*)C)[((size_t)(row + 8) * N + col) >> 1] = cvt2h(acc[mt][nt][2], acc[mt][nt][3]);
        }
}

// ---------------------------------------------------------------------------
// Fused LayerNorm + convert from fp16 qkv: [b,s,3,h,d] ->
//   q: LN, *0.125 -> qh [b,h,s,d] ; k: LN -> kh ; v: copy -> vh
// ---------------------------------------------------------------------------
__global__ __launch_bounds__(256) void ln_split_kernel(
    const __half* __restrict__ qkv,
    const float* __restrict__ qs, const float* __restrict__ qbias,
    const float* __restrict__ ks, const float* __restrict__ kbias,
    __half* __restrict__ qh, __half* __restrict__ kh, __half* __restrict__ vh)
{
    const int w = (int)((blockIdx.x * 256u + threadIdx.x) >> 5);   // row over B*S*H
    const int lane = threadIdx.x & 31;
    const int h = w & 15;
    const int bs = w >> 4;
    const int b = bs >> 11, s = bs & 2047;
    const __half* p = qkv + (size_t)bs * 3072 + h * 64 + lane * 2;

    float2 qv = __half22float2(*(const __half2*)p);
    float2 kv = __half22float2(*(const __half2*)(p + 1024));
    uint32_t vw = *(const uint32_t*)(p + 2048);

    float sq = qv.x + qv.y, qq = qv.x * qv.x + qv.y * qv.y;
    float sk = kv.x + kv.y, kk = kv.x * kv.x + kv.y * kv.y;
#pragma unroll
    for (int off = 16; off; off >>= 1) {
        sq += __shfl_xor_sync(0xffffffffu, sq, off);
        qq += __shfl_xor_sync(0xffffffffu, qq, off);
        sk += __shfl_xor_sync(0xffffffffu, sk, off);
        kk += __shfl_xor_sync(0xffffffffu, kk, off);
    }
    float qm = sq * (1.f / 64.f);
    float qr = rsqrtf(fmaxf(qq * (1.f / 64.f) - qm * qm, 0.f) + 1e-5f);
    float km = sk * (1.f / 64.f);
    float kr = rsqrtf(fmaxf(kk * (1.f / 64.f) - km * km, 0.f) + 1e-5f);

    float2 scq = *(const float2*)(qs + lane * 2);
    float2 biq = *(const float2*)(qbias + lane * 2);
    float2 sck = *(const float2*)(ks + lane * 2);
    float2 bik = *(const float2*)(kbias + lane * 2);

    float qnx = ((qv.x - qm) * qr * scq.x + biq.x) * 0.125f;
    float qny = ((qv.y - qm) * qr * scq.y + biq.y) * 0.125f;
    float knx = (kv.x - km) * kr * sck.x + bik.x;
    float kny = (kv.y - km) * kr * sck.y + bik.y;

    const size_t o = (((size_t)(b * TH + h)) * TS + s) * 64 + lane * 2;
    *(uint32_t*)(qh + o) = cvt2h(qnx, qny);
    *(uint32_t*)(kh + o) = cvt2h(knx, kny);
    *(uint32_t*)(vh + o) = vw;
}

// ---------------------------------------------------------------------------
// Flash attention, MAX-FREE softmax (|logit| <= 8 from LN geometry).
// CTA: 128 q-rows, 4 warps, warp = m32 x n64. K-tile = 64 keys, processed as
// TWO 32-key halves {S-MMA -> exp/l/T -> PV} to shrink s4's live range
// (64 -> 32 regs) so 3 CTAs/SM fit WITHOUT forced spills (R16 lesson:
// never cap regs below natural demand). NO minBlocks forcing.
// Smem: double-buffered {K, V} (16KB/stage) + persistent Q (16KB) = 48KB.
// ---------------------------------------------------------------------------
#define AB_K  0
#define AB_VH 8192
#define AB_BUF 16384
#define AQ_H 32768
#define ATTN_SMEM 49152

__global__ __launch_bounds__(128) void attn_mma_kernel(
    const __half* __restrict__ qhg, const __half* __restrict__ khg,
    const __half* __restrict__ vhg,
    __half* __restrict__ cs, float* __restrict__ ent)
{
    extern __shared__ char smA[];
    __shared__ float red[4];
    const uint32_t sb = smem_u32(smA);

    const int tid = threadIdx.x, wid = tid >> 5, lane = tid & 31;
    const int qb0 = blockIdx.x << 7;           // 128 q rows per CTA
    const int h = blockIdx.y, b = blockIdx.z;
    const size_t bh = ((size_t)(b * TH + h)) * TS * 64;

    // ---- prologue: Q (128 rows, 16KB) -> persistent region (group 0) ----
#pragma unroll
    for (int j = 0; j < 8; ++j) {
        int c = tid + 128 * j;
        int row = c >> 3, k8 = c & 7;
        size_t g = bh + (size_t)(qb0 + row) * 64 + (k8 << 3);
        uint32_t so = sw128((uint32_t)((row << 7) + (k8 << 4)));
        cp16(sb + AQ_H + so, qhg + g);
    }
    cp_commit();

    auto load_kv = [&](int kt) {
        const uint32_t bufb = sb + (uint32_t)(kt & 1) * AB_BUF;
#pragma unroll
        for (int j = 0; j < 4; ++j) {
            int c = tid + 128 * j;
            int row = c >> 3, k8 = c & 7;
            size_t g = bh + (size_t)((kt << 6) + row) * 64 + (k8 << 3);
            uint32_t so = sw128((uint32_t)((row << 7) + (k8 << 4)));
            cp16(bufb + AB_K + so, khg + g);
            cp16(bufb + AB_VH + so, vhg + g);
        }
        cp_commit();
    };
    load_kv(0);

    cp_wait<1>();                              // Q group retired (FIFO)
    __syncthreads();

    // ---- extract Q A-fragments (2 m16 sub-tiles) ----
    uint32_t qh[2][4][4];
    {
        const int cb = (lane >> 4) << 4;
#pragma unroll
        for (int mt = 0; mt < 2; ++mt) {
            const int row = (wid << 5) + (mt << 4) + (lane & 15);
#pragma unroll
            for (int s = 0; s < 4; ++s) {
                uint32_t so = sw128((uint32_t)(row * 128 + s * 32 + cb));
                ldm_x4(sb + AQ_H + so, qh[mt][s]);
            }
        }
    }

    float o[2][8][4];
#pragma unroll
    for (int mt = 0; mt < 2; ++mt)
#pragma unroll
        for (int nt = 0; nt < 8; ++nt)
#pragma unroll
            for (int r = 0; r < 4; ++r) o[mt][nt][r] = 0.f;
    float l2[2][2] = {{0.f, 0.f}, {0.f, 0.f}};
    float T2[2][2] = {{0.f, 0.f}, {0.f, 0.f}};

    for (int kt = 0; kt < TS / 64; ++kt) {
        if (kt + 1 < TS / 64) { load_kv(kt + 1); cp_wait<1>(); }
        else                  { cp_wait<0>(); }
        __syncthreads();
        const uint32_t bufb = sb + (uint32_t)(kt & 1) * AB_BUF;

#pragma unroll
        for (int hk = 0; hk < 2; ++hk) {       // 32-key half
            // ---- S = Q K^T for this half (s4 live range: 32 regs) ----
            float s4[2][4][4];
#pragma unroll
            for (int mt = 0; mt < 2; ++mt)
#pragma unroll
                for (int nt = 0; nt < 4; ++nt)
#pragma unroll
                    for (int r = 0; r < 4; ++r) s4[mt][nt][r] = 0.f;

#pragma unroll
            for (int s = 0; s < 4; ++s) {
                uint32_t kb[2][4];
#pragma unroll
                for (int p = 0; p < 2; ++p) {
                    const int kb_row = ((lane >> 4) << 3) + (lane & 7);
                    const int kb_c = (lane >> 3) & 1;
                    const int prow = (hk << 1) + p;
                    uint32_t so = sw128((uint32_t)(((prow << 4) + kb_row) * 128
                                                   + s * 32 + kb_c * 16));
                    ldm_x4(bufb + AB_K + so, kb[p]);
                }
#pragma unroll
                for (int mt = 0; mt < 2; ++mt)
#pragma unroll
                    for (int nt = 0; nt < 4; ++nt)
                        mma16816(s4[mt][nt], qh[mt][s], &kb[nt >> 1][(nt & 1) << 1]);
            }

            // ---- max-free softmax accumulation (thread-local l, T) ----
#pragma unroll
            for (int mt = 0; mt < 2; ++mt) {
#pragma unroll
                for (int nt = 0; nt < 4; ++nt) {
                    float d0 = s4[mt][nt][0], d1 = s4[mt][nt][1];
                    float d2 = s4[mt][nt][2], d3 = s4[mt][nt][3];
                    float e0 = __expf(d0), e1 = __expf(d1);
                    float e2 = __expf(d2), e3 = __expf(d3);
                    s4[mt][nt][0] = e0; s4[mt][nt][1] = e1;
                    s4[mt][nt][2] = e2; s4[mt][nt][3] = e3;
                    l2[mt][0] += e0 + e1;
                    l2[mt][1] += e2 + e3;
                    T2[mt][0] = fmaf(e0, d0, fmaf(e1, d1, T2[mt][0]));
                    T2[mt][1] = fmaf(e2, d2, fmaf(e3, d3, T2[mt][1]));
                }
            }

            // ---- O += P V for this half (2 k16 chunks) ----
#pragma unroll
            for (int sl = 0; sl < 2; ++sl) {
                uint32_t pa[2][4];
#pragma unroll
                for (int mt = 0; mt < 2; ++mt) {
                    pa[mt][0] = cvt2h(s4[mt][2 * sl][0],     s4[mt][2 * sl][1]);
                    pa[mt][1] = cvt2h(s4[mt][2 * sl][2],     s4[mt][2 * sl][3]);
                    pa[mt][2] = cvt2h(s4[mt][2 * sl + 1][0], s4[mt][2 * sl + 1][1]);
                    pa[mt][3] = cvt2h(s4[mt][2 * sl + 1][2], s4[mt][2 * sl + 1][3]);
                }
                uint32_t vb[4][4];
#pragma unroll
                for (int p2 = 0; p2 < 4; ++p2) {
                    const int v_key = (((lane >> 3) & 1) << 3) + (lane & 7);
                    const int v_d = (lane >> 4) << 3;
                    const int sg = (hk << 1) + sl;
                    uint32_t so = sw128((uint32_t)(((sg << 4) + v_key) * 128
                                                   + ((p2 << 4) + v_d) * 2));
                    ldm_x4_t(bufb + AB_VH + so, vb[p2]);
                }
#pragma unroll
                for (int mt = 0; mt < 2; ++mt)
#pragma unroll
                    for (int nt = 0; nt < 8; ++nt)
                        mma16816(o[mt][nt], pa[mt], &vb[nt >> 1][(nt & 1) << 1]);
            }
        }
        __syncthreads();   // all warps done reading buf before next overwrite
    }

    // ---- final quad reduction of l, T (once, not per tile) ----
#pragma unroll
    for (int mt = 0; mt < 2; ++mt)
#pragma unroll
        for (int hf = 0; hf < 2; ++hf) {
#pragma unroll
            for (int off = 1; off <= 2; off <<= 1) {
                l2[mt][hf] += __shfl_xor_sync(0xffffffffu, l2[mt][hf], off);
                T2[mt][hf] += __shfl_xor_sync(0xffffffffu, T2[mt][hf], off);
            }
        }

    // ---- write context as single fp16 (feeds proj GEMM directly) ----
#pragma unroll
    for (int mt = 0; mt < 2; ++mt) {
        float rl0 = 1.f / l2[mt][0], rl1 = 1.f / l2[mt][1];
        const int r0 = qb0 + (wid << 5) + (mt << 4) + (lane >> 2);
        const int cb = (h << 6) + ((lane & 3) << 1);
#pragma unroll
        for (int nt = 0; nt < 8; ++nt) {
            const int col = cb + (nt << 3);
            const size_t i0 = ((size_t)(b * TS + r0) * 1024 + col) >> 1;
            const size_t i1 = ((size_t)(b * TS + r0 + 8) * 1024 + col) >> 1;
            ((uint32_t*)cs)[i0] = cvt2h(o[mt][nt][0] * rl0, o[mt][nt][1] * rl0);
            ((uint32_t*)cs)[i1] = cvt2h(o[mt][nt][2] * rl1, o[mt][nt][3] * rl1);
        }
    }

    // ---- entropy: per-row log(l) - T/l, reduce, one atomic per CTA ----
    float e = 0.f;
    if ((lane & 3) == 0) {
#pragma unroll
        for (int mt = 0; mt < 2; ++mt)
            e += (__logf(l2[mt][0]) - T2[mt][0] / l2[mt][0]) +
                 (__logf(l2[mt][1]) - T2[mt][1] / l2[mt][1]);
    }
#pragma unroll
    for (int off = 16; off; off >>= 1) e += __shfl_xor_sync(0xffffffffu, e, off);
    if (lane == 0) red[wid] = e;
    __syncthreads();
    if (tid == 0) {
        float esum = red[0] + red[1] + red[2] + red[3];
        const float ent_scale = (float)(1.0 / (7.6246189861593985 * (double)(TH * TS)));
        atomicAdd(ent + b, esum * ent_scale);
    }
}

// ---------------------------------------------------------------------------
extern "C" void kernel_launch(void* const* d_in, const int* in_sizes, int n_in,
                              void* d_out, int out_size)
{
    const float* x       = (const float*)d_in[0];
    const float* w_qkv   = (const float*)d_in[1];
    const float* w_proj  = (const float*)d_in[2];
    const float* q_scale = (const float*)d_in[3];
    const float* q_bias  = (const float*)d_in[4];
    const float* k_scale = (const float*)d_in[5];
    const float* k_bias  = (const float*)d_in[6];
    float* out = (float*)d_out;

    float* entpad;
    cudaGetSymbolAddress((void**)&entpad, g_entpad);
    __half *qkvh, *xs, *wq, *cs, *wp;
    __half *qh2, *kh2, *vh2;
    cudaGetSymbolAddress((void**)&qkvh, g_qkvh);
    cudaGetSymbolAddress((void**)&xs, g_xs);
    cudaGetSymbolAddress((void**)&wq, g_wq);
    cudaGetSymbolAddress((void**)&cs, g_cs);
    cudaGetSymbolAddress((void**)&wp, g_wp);
    cudaGetSymbolAddress((void**)&qh2, g_qh2);
    cudaGetSymbolAddress((void**)&kh2, g_kh2);
    cudaGetSymbolAddress((void**)&vh2, g_vh2);

    cudaFuncSetAttribute(gemm_s_kernel, cudaFuncAttributeMaxDynamicSharedMemorySize, GEMM_S_SMEM);
    cudaFuncSetAttribute(gemm_sh_kernel, cudaFuncAttributeMaxDynamicSharedMemorySize, GEMM_S_SMEM);
    cudaFuncSetAttribute(attn_mma_kernel, cudaFuncAttributeMaxDynamicSharedMemorySize, ATTN_SMEM);

    const int BS = TB * TS;                 // 8192
    const size_t main_elems = (size_t)BS * TC;
    float* ent = (out_size >= (int)(main_elems + TB)) ? (out + main_elems) : entpad;

    // 1) fused prep: x->fp16, w transposes, entropy zero
    prep_kernel<<<PREP_BLOCKS, 256>>>((const float4*)x, xs, w_qkv, wq, w_proj, wp, ent);

    // 2) QKV projection -> fp16 qkv: [8192,1024] @ [1024,3072]
    gemm_sh_kernel<<<dim3(3 * TC / 128, BS / 128), 256, GEMM_S_SMEM>>>(
        xs, wq, qkvh, BS, 3 * TC, TC);

    // 3) fused LayerNorm + convert -> fp16 q/k/v in [b,h,s,d]
    ln_split_kernel<<<(TB * TS * TH) / 8, 256>>>(
        qkvh, q_scale, q_bias, k_scale, k_bias, qh2, kh2, vh2);

    // 4) fused attention (max-free softmax, halved S live-range) -> cs fp16
    attn_mma_kernel<<<dim3(TS / 128, TH, TB), 128, ATTN_SMEM>>>(
        qh2, kh2, vh2, cs, ent);

    // 5) output projection (single fp16): [8192,1024] @ [1024,1024]
    gemm_s_kernel<<<dim3(TC / 128, BS / 128), 256, GEMM_S_SMEM>>>(
        cs, wp, out, BS, TC, TC);
}